// round 12
// baseline (speedup 1.0000x reference)
#include <cuda_runtime.h>
#include <cuda_bf16.h>
#include <math.h>
#include <stdint.h>

#define Bsz   32
#define Tlen  128
#define Ulen  64
#define ENCD  512
#define DECD  512
#define ATTND 256
#define EMBD  256
#define VOCAB 32000
#define GIN   768     // EMB + ENC
#define G3    1536    // 3 * DEC
#define HCW   1024    // DEC + ENC

#define NB  128
#define NTD 512        // decoder threads per CTA (16 warps)

// ---------------- scratch (static device globals; no allocation) ----------------
__device__ float g_Wh[Bsz * Tlen * ATTND];          // 4 MB
__device__ float g_WsT[ATTND * DECD];               // W_s transposed: [col][d]
__device__ float g_c[Bsz * ENCD];
__device__ float g_h[Bsz * DECD];
__device__ float g_gh[Bsz * G3];
__device__ unsigned g_barc;                          // zero-init
__device__ unsigned g_barg;                          // zero-init

// bf16 hi/lo split operands for the tensor-core logits GEMM
__device__ __nv_bfloat16 g_Whi[(size_t)VOCAB * HCW];   // 65.5 MB
__device__ __nv_bfloat16 g_Wlo[(size_t)VOCAB * HCW];   // 65.5 MB
__device__ __nv_bfloat16 g_Ahi[(size_t)Bsz * Ulen * HCW];  // 4 MB
__device__ __nv_bfloat16 g_Alo[(size_t)Bsz * Ulen * HCW];  // 4 MB

// ---------------- helpers ----------------
__device__ __forceinline__ float dot4(float4 a, float4 b) {
    return fmaf(a.x, b.x, fmaf(a.y, b.y, fmaf(a.z, b.z, a.w * b.w)));
}
__device__ __forceinline__ float wsum(float x) {
    x += __shfl_xor_sync(0xffffffffu, x, 16);
    x += __shfl_xor_sync(0xffffffffu, x, 8);
    x += __shfl_xor_sync(0xffffffffu, x, 4);
    x += __shfl_xor_sync(0xffffffffu, x, 2);
    x += __shfl_xor_sync(0xffffffffu, x, 1);
    return x;
}
__device__ __forceinline__ float wmax(float x) {
    x = fmaxf(x, __shfl_xor_sync(0xffffffffu, x, 16));
    x = fmaxf(x, __shfl_xor_sync(0xffffffffu, x, 8));
    x = fmaxf(x, __shfl_xor_sync(0xffffffffu, x, 4));
    x = fmaxf(x, __shfl_xor_sync(0xffffffffu, x, 2));
    x = fmaxf(x, __shfl_xor_sync(0xffffffffu, x, 1));
    return x;
}

__device__ __forceinline__ void grid_barrier() {
    __syncthreads();
    if (threadIdx.x == 0) {
        volatile unsigned* genp = &g_barg;
        unsigned gen = *genp;
        __threadfence();
        unsigned arrived = atomicAdd(&g_barc, 1u);
        if (arrived == NB - 1) {
            g_barc = 0;
            __threadfence();
            *genp = gen + 1;
        } else {
            while (*genp == gen) { __nanosleep(32); }
            __threadfence();
        }
    }
    __syncthreads();
}

__device__ __forceinline__ void cpa16(uint32_t dst, const void* src) {
    asm volatile("cp.async.cg.shared.global [%0], [%1], 16;" :: "r"(dst), "l"(src));
}
__device__ __forceinline__ uint32_t smem_u32(const void* p) {
    uint32_t a;
    asm("{ .reg .u64 t; cvta.to.shared.u64 t, %1; cvt.u32.u64 %0, t; }" : "=r"(a) : "l"(p));
    return a;
}
__device__ __forceinline__ void ldsm4(uint32_t* r, uint32_t addr) {
    asm volatile("ldmatrix.sync.aligned.m8n8.x4.shared.b16 {%0,%1,%2,%3}, [%4];"
                 : "=r"(r[0]), "=r"(r[1]), "=r"(r[2]), "=r"(r[3]) : "r"(addr));
}

// ---------------- kernel 1: Wh = enc_out @ W_h  (tiled, W_h staged in smem) ----------------
// 128 blocks x 512 threads; block handles 32 bt-rows; k tiled in 8 chunks of 64.
#define WH_SMEM ((32 * 64 + 64 * ATTND) * 4)   // sE 8KB + sW 64KB = 72KB
__global__ __launch_bounds__(512) void wh_kernel(const float* __restrict__ enc_out,
                                                 const float* __restrict__ W_h) {
    extern __shared__ float ws[];
    float* sE = ws;            // [32][64]
    float* sW = ws + 32 * 64;  // [64][256]
    const int tid  = threadIdx.x;
    const int col  = tid & 255;
    const int half = tid >> 8;           // 0..1
    const int r0   = half * 16;
    const int bt0  = blockIdx.x * 32;

    float acc[16];
    #pragma unroll
    for (int r = 0; r < 16; r++) acc[r] = 0.f;

    for (int kc = 0; kc < 8; kc++) {
        // load sE: 512 float4 (one per thread)
        {
            const int row = tid >> 4, kq = tid & 15;
            *(float4*)&sE[row * 64 + kq * 4] =
                *(const float4*)&enc_out[(size_t)(bt0 + row) * ENCD + kc * 64 + kq * 4];
        }
        // load sW: 4096 float4, 8 per thread
        #pragma unroll
        for (int it = 0; it < 8; it++) {
            const int idx = tid + it * 512;
            const int kk = idx >> 6, cq = idx & 63;
            *(float4*)&sW[kk * 256 + cq * 4] =
                *(const float4*)&W_h[(size_t)(kc * 64 + kk) * ATTND + cq * 4];
        }
        __syncthreads();
        #pragma unroll 4
        for (int kk = 0; kk < 64; kk++) {
            const float w = sW[kk * 256 + col];
            #pragma unroll
            for (int r = 0; r < 16; r++)
                acc[r] = fmaf(sE[(r0 + r) * 64 + kk], w, acc[r]);
        }
        __syncthreads();
    }
    #pragma unroll
    for (int r = 0; r < 16; r++)
        g_Wh[(size_t)(bt0 + r0 + r) * ATTND + col] = acc[r];
}

// ---------------- kernel: transpose W_s -> g_WsT[col][d] ----------------
__global__ __launch_bounds__(256) void transWs_kernel(const float* __restrict__ W_s) {
    const int d = blockIdx.x;        // 512
    const int c = threadIdx.x;       // 256
    g_WsT[(size_t)c * DECD + d] = W_s[(size_t)d * ATTND + c];
}

// ---------------- conversion kernel: W fp32 -> bf16 hi/lo split ----------------
__global__ __launch_bounds__(256) void convW_kernel(const float* __restrict__ W) {
    const size_t n4 = (size_t)VOCAB * HCW / 4;
    const size_t stride = (size_t)gridDim.x * blockDim.x;
    for (size_t i = (size_t)blockIdx.x * blockDim.x + threadIdx.x; i < n4; i += stride) {
        float4 v = ((const float4*)W)[i];
        __nv_bfloat16 h0 = __float2bfloat16(v.x);
        __nv_bfloat16 h1 = __float2bfloat16(v.y);
        __nv_bfloat16 h2 = __float2bfloat16(v.z);
        __nv_bfloat16 h3 = __float2bfloat16(v.w);
        __nv_bfloat162 H01, H23, L01, L23;
        H01.x = h0; H01.y = h1; H23.x = h2; H23.y = h3;
        L01.x = __float2bfloat16(v.x - __bfloat162float(h0));
        L01.y = __float2bfloat16(v.y - __bfloat162float(h1));
        L23.x = __float2bfloat16(v.z - __bfloat162float(h2));
        L23.y = __float2bfloat16(v.w - __bfloat162float(h3));
        ((__nv_bfloat162*)g_Whi)[2 * i]     = H01;
        ((__nv_bfloat162*)g_Whi)[2 * i + 1] = H23;
        ((__nv_bfloat162*)g_Wlo)[2 * i]     = L01;
        ((__nv_bfloat162*)g_Wlo)[2 * i + 1] = L23;
    }
}

// ---------------- kernel 2: persistent decoder, 2 grid barriers per step ----------------
// smem float layout:
//   [0,8192)        swhh  : Whh slice, 16 rows x 512  (CTA 32<=ci<128)
//   [8192,17408)    swih  : Wih slice, 12 rows x 768  (all CTAs; d0=4ci)
//   [17408,33792)   sh    : gh CTAs: full h 32x512; attention CTAs: sh[0..512)=h[b]
//   [33792,33920)   se
//   [33920,34048)   salpha
//   [34048,34304)   swsb
//   [34304,34560)   sv
//   [34560,34624)   sred
#define SMEM_DEC (34624 * 4)

__global__ __launch_bounds__(NTD) void decoder_kernel(
    const float* __restrict__ enc_out, const int* __restrict__ enc_mask,
    const int* __restrict__ y_in, const float* __restrict__ emb,
    const float* __restrict__ v,
    const float* __restrict__ Wih, const float* __restrict__ Whh,
    const float* __restrict__ bih, const float* __restrict__ bhh,
    float* __restrict__ out_alpha)
{
    extern __shared__ float sm[];
    float* swhh   = sm;
    float* swih   = sm + 8192;
    float* sh     = sm + 17408;
    float* se     = sm + 33792;
    float* salpha = sm + 33920;
    float* swsb   = sm + 34048;
    float* sv     = sm + 34304;
    float* sred   = sm + 34560;

    const int ci   = blockIdx.x;
    const int tid  = threadIdx.x;
    const int lane = tid & 31;
    const int wid  = tid >> 5;

    // ---- one-time: weight slices into smem ----
    {
        const int d0 = ci * 4;
        for (int i = tid; i < 9216; i += NTD) {
            const int r = i / GIN, k = i - r * GIN;
            const int g = r >> 2, dL = r & 3;
            swih[i] = Wih[(size_t)(g * DECD + d0 + dL) * GIN + k];
        }
    }
    if (ci >= 32) {
        const int r0 = (ci - 32) * 16;
        for (int i = tid; i < 8192; i += NTD)
            swhh[i] = Whh[(size_t)(r0 + (i >> 9)) * DECD + (i & 511)];
    }
    if (ci < 32) {
        for (int i = tid; i < ATTND; i += NTD) sv[i] = v[i];
    }
    for (int i = ci * NTD + tid; i < Bsz * DECD; i += NB * NTD) g_h[i] = 0.f;
    grid_barrier();

    for (int u = 0; u < Ulen; u++) {
        // ======= Phase 1: attention (CTAs 0..31) || gh (CTAs 32..127) =======
        if (ci < 32) {
            const int b = ci;
            // h[b] into sh[0..512)
            sh[tid] = g_h[b * DECD + tid];
            __syncthreads();
            // Ws[b][col] = dot(h[b], WsT[col]) ; warp per 16 cols
            {
                const float4* hb4 = (const float4*)sh;
                #pragma unroll
                for (int cc = 0; cc < 16; cc++) {
                    const int col = wid * 16 + cc;
                    const float4* wt = (const float4*)(g_WsT + (size_t)col * DECD);
                    float acc = 0.f;
                    #pragma unroll
                    for (int q = 0; q < 4; q++) {
                        const int i4 = q * 32 + lane;
                        acc += dot4(hb4[i4], wt[i4]);
                    }
                    acc = wsum(acc);
                    if (lane == 0) swsb[col] = acc;
                }
            }
            __syncthreads();
            // e[t] = v . tanh(Wh[b,t,:] + Ws[b,:]), masked
            #pragma unroll
            for (int j = 0; j < 8; j++) {
                const int t = wid * 8 + j;
                const float4* whp = (const float4*)(g_Wh + ((size_t)b * Tlen + t) * ATTND);
                const float4* wsp = (const float4*)swsb;
                const float4* vp  = (const float4*)sv;
                float acc = 0.f;
                #pragma unroll
                for (int q = 0; q < 2; q++) {
                    const int i4 = q * 32 + lane;
                    float4 w4 = whp[i4], s4 = wsp[i4], v4 = vp[i4];
                    acc += v4.x * tanhf(w4.x + s4.x);
                    acc += v4.y * tanhf(w4.y + s4.y);
                    acc += v4.z * tanhf(w4.z + s4.z);
                    acc += v4.w * tanhf(w4.w + s4.w);
                }
                acc = wsum(acc);
                if (lane == 0) se[t] = enc_mask[b * Tlen + t] ? acc : -INFINITY;
            }
            __syncthreads();
            // softmax over 128 t
            if (tid < 128) {
                float m = wmax(se[tid]);
                if (lane == 0) sred[wid] = m;
            }
            __syncthreads();
            if (tid == 0)
                sred[8] = fmaxf(fmaxf(sred[0], sred[1]), fmaxf(sred[2], sred[3]));
            __syncthreads();
            if (tid < 128) {
                const float p = expf(se[tid] - sred[8]);
                salpha[tid] = p;
                const float s = wsum(p);
                if (lane == 0) sred[16 + wid] = s;
            }
            __syncthreads();
            if (tid == 0)
                sred[9] = sred[16] + sred[17] + sred[18] + sred[19];
            __syncthreads();
            if (tid < 128) {
                const float al = salpha[tid] / sred[9];
                salpha[tid] = al;
                out_alpha[((size_t)b * Ulen + u) * Tlen + tid] = al;
            }
            __syncthreads();
            // c[col] = sum_t alpha[t] * enc_out[b,t,col]
            {
                const float* ep = enc_out + (size_t)b * Tlen * ENCD + tid;
                float a0 = 0.f, a1 = 0.f, a2 = 0.f, a3 = 0.f;
                #pragma unroll 4
                for (int t = 0; t < Tlen; t += 4) {
                    a0 = fmaf(salpha[t + 0], ep[(t + 0) * ENCD], a0);
                    a1 = fmaf(salpha[t + 1], ep[(t + 1) * ENCD], a1);
                    a2 = fmaf(salpha[t + 2], ep[(t + 2) * ENCD], a2);
                    a3 = fmaf(salpha[t + 3], ep[(t + 3) * ENCD], a3);
                }
                const float cc = (a0 + a1) + (a2 + a3);
                g_c[b * ENCD + tid] = cc;
                const size_t hx = ((size_t)b * Ulen + u) * HCW + DECD + tid;
                const __nv_bfloat16 hi = __float2bfloat16(cc);
                g_Ahi[hx] = hi;
                g_Alo[hx] = __float2bfloat16(cc - __bfloat162float(hi));
            }
        } else {
            // gh CTAs: copy full h, then 16 Whh rows, warp = batch pair
            float4* sh4 = (float4*)sh;
            const float4* gh4 = (const float4*)g_h;
            for (int i = tid; i < (Bsz * DECD) / 4; i += NTD) sh4[i] = gh4[i];
            __syncthreads();
            const int r0 = (ci - 32) * 16;
            const int b0 = wid * 2, b1 = b0 + 1;
            float4 h0r[4], h1r[4];
            const float4* h0p = (const float4*)(sh + b0 * DECD);
            const float4* h1p = (const float4*)(sh + b1 * DECD);
            #pragma unroll
            for (int q = 0; q < 4; q++) {
                h0r[q] = h0p[q * 32 + lane];
                h1r[q] = h1p[q * 32 + lane];
            }
            #pragma unroll 2
            for (int rL = 0; rL < 16; rL++) {
                const float4* wr = (const float4*)(swhh + rL * DECD);
                float a0 = 0.f, a1 = 0.f;
                #pragma unroll
                for (int q = 0; q < 4; q++) {
                    const float4 w4 = wr[q * 32 + lane];
                    a0 += dot4(h0r[q], w4);
                    a1 += dot4(h1r[q], w4);
                }
                a0 = wsum(a0); a1 = wsum(a1);
                if (lane == 0) {
                    const float bb = bhh[r0 + rL];
                    g_gh[b0 * G3 + r0 + rL] = a0 + bb;
                    g_gh[b1 * G3 + r0 + rL] = a1 + bb;
                }
            }
        }
        grid_barrier();

        // ================= Phase 2 (D): GRU gates, h_new (all 128 CTAs) ==========
        {
            const int d0 = ci * 4;
            const int b0 = wid * 2, b1 = b0 + 1;
            float4 x0[6], x1[6];
            {
                const int y0 = y_in[b0 * Ulen + u];
                const int y1 = y_in[b1 * Ulen + u];
                const float4* e0 = (const float4*)(emb + (size_t)y0 * EMBD);
                const float4* e1 = (const float4*)(emb + (size_t)y1 * EMBD);
                const float4* c0p = (const float4*)(g_c + b0 * ENCD);
                const float4* c1p = (const float4*)(g_c + b1 * ENCD);
                #pragma unroll
                for (int q = 0; q < 6; q++) {
                    const int i4 = q * 32 + lane;
                    x0[q] = (i4 < 64) ? e0[i4] : c0p[i4 - 64];
                    x1[q] = (i4 < 64) ? e1[i4] : c1p[i4 - 64];
                }
            }
            #pragma unroll
            for (int dL = 0; dL < 4; dL++) {
                const int d = d0 + dL;
                float ir0 = 0.f, iz0 = 0.f, in0 = 0.f;
                float ir1 = 0.f, iz1 = 0.f, in1 = 0.f;
                const float4* wr = (const float4*)(swih + (0 * 4 + dL) * GIN);
                const float4* wz = (const float4*)(swih + (1 * 4 + dL) * GIN);
                const float4* wn = (const float4*)(swih + (2 * 4 + dL) * GIN);
                #pragma unroll
                for (int q = 0; q < 6; q++) {
                    const int i4 = q * 32 + lane;
                    const float4 a = wr[i4], z = wz[i4], n = wn[i4];
                    ir0 += dot4(x0[q], a); ir1 += dot4(x1[q], a);
                    iz0 += dot4(x0[q], z); iz1 += dot4(x1[q], z);
                    in0 += dot4(x0[q], n); in1 += dot4(x1[q], n);
                }
                ir0 = wsum(ir0); iz0 = wsum(iz0); in0 = wsum(in0);
                ir1 = wsum(ir1); iz1 = wsum(iz1); in1 = wsum(in1);
                if (lane == 0) {
                    const float br = bih[d], bz = bih[DECD + d], bn2 = bih[2 * DECD + d];
                    {
                        const float hr = g_gh[b0 * G3 + d];
                        const float hz = g_gh[b0 * G3 + DECD + d];
                        const float hn = g_gh[b0 * G3 + 2 * DECD + d];
                        const float r = 1.f / (1.f + expf(-(ir0 + br + hr)));
                        const float z = 1.f / (1.f + expf(-(iz0 + bz + hz)));
                        const float n = tanhf(in0 + bn2 + r * hn);
                        const float hp = g_h[b0 * DECD + d];
                        const float hnew = (1.f - z) * n + z * hp;
                        g_h[b0 * DECD + d] = hnew;
                        const size_t hx = ((size_t)b0 * Ulen + u) * HCW + d;
                        const __nv_bfloat16 hi = __float2bfloat16(hnew);
                        g_Ahi[hx] = hi;
                        g_Alo[hx] = __float2bfloat16(hnew - __bfloat162float(hi));
                    }
                    {
                        const float hr = g_gh[b1 * G3 + d];
                        const float hz = g_gh[b1 * G3 + DECD + d];
                        const float hn = g_gh[b1 * G3 + 2 * DECD + d];
                        const float r = 1.f / (1.f + expf(-(ir1 + br + hr)));
                        const float z = 1.f / (1.f + expf(-(iz1 + bz + hz)));
                        const float n = tanhf(in1 + bn2 + r * hn);
                        const float hp = g_h[b1 * DECD + d];
                        const float hnew = (1.f - z) * n + z * hp;
                        g_h[b1 * DECD + d] = hnew;
                        const size_t hx = ((size_t)b1 * Ulen + u) * HCW + d;
                        const __nv_bfloat16 hi = __float2bfloat16(hnew);
                        g_Ahi[hx] = hi;
                        g_Alo[hx] = __float2bfloat16(hnew - __bfloat162float(hi));
                    }
                }
            }
        }
        grid_barrier();
    }
}

// ---------------- kernel 3: bf16-split logits GEMM, 3-stage cp.async pipeline ----------------
#define BM 128
#define BN 128
#define BKE 64
#define NKC 48
#define TPAD 8
#define TSTR (BKE + TPAD)
#define TILEB (128 * TSTR * 2)
#define STAGEB (2 * TILEB)          // 36864
#define NSTAGE 3
#define GSMEM (NSTAGE * STAGEB)     // 110592

__device__ __forceinline__ void mma16816(float* c, const uint32_t* a, uint32_t b0, uint32_t b1) {
    asm volatile(
        "mma.sync.aligned.m16n8k16.row.col.f32.bf16.bf16.f32 "
        "{%0,%1,%2,%3}, {%4,%5,%6,%7}, {%8,%9}, {%0,%1,%2,%3};"
        : "+f"(c[0]), "+f"(c[1]), "+f"(c[2]), "+f"(c[3])
        : "r"(a[0]), "r"(a[1]), "r"(a[2]), "r"(a[3]), "r"(b0), "r"(b1));
}

__global__ __launch_bounds__(256, 2) void tc_gemm(const float* __restrict__ bias,
                                                  float* __restrict__ C)
{
    extern __shared__ char smemc[];
    const uint32_t sb = smem_u32(smemc);
    const int tid  = threadIdx.x;
    const int wid  = tid >> 5;
    const int lane = tid & 31;
    const int warp_m = wid >> 2;
    const int warp_n = wid & 3;
    const int bm = blockIdx.x * BM;
    const int bn = blockIdx.y * BN;

    const int lrow = lane & 15;
    const int lcol = (lane >> 4) * 16;

    float acc[4][4][4];
    #pragma unroll
    for (int i = 0; i < 4; i++)
        #pragma unroll
        for (int j = 0; j < 4; j++)
            #pragma unroll
            for (int r = 0; r < 4; r++) acc[i][j][r] = 0.f;

    auto load_chunk = [&](int stage, int kc) {
        const int p  = kc >> 4;
        const int ko = (kc & 15) * BKE;
        const __nv_bfloat16* Asrc = (p < 2) ? g_Ahi : g_Alo;
        const __nv_bfloat16* Bsrc = (p == 1) ? g_Wlo : g_Whi;
        const uint32_t sA = sb + stage * STAGEB;
        const uint32_t sB = sA + TILEB;
        #pragma unroll
        for (int it = 0; it < 8; it++) {
            const int i = tid + it * 256;
            const int row  = (i >> 3) & 127;
            const int unit = i & 7;
            const uint32_t doff = (uint32_t)(row * (TSTR * 2) + unit * 16);
            if (i < 1024) {
                cpa16(sA + doff, Asrc + (size_t)(bm + row) * HCW + ko + unit * 8);
            } else {
                cpa16(sB + doff, Bsrc + (size_t)(bn + row) * HCW + ko + unit * 8);
            }
        }
        asm volatile("cp.async.commit_group;");
    };

    load_chunk(0, 0);
    load_chunk(1, 1);

    #pragma unroll 1
    for (int kc = 0; kc < NKC; kc++) {
        if (kc == NKC - 1) {
            asm volatile("cp.async.wait_group 0;" ::: "memory");
        } else {
            asm volatile("cp.async.wait_group 1;" ::: "memory");
        }
        __syncthreads();   // chunk kc visible to all; stage (kc+2)%3 free (computed at kc-1)

        if (kc + 2 < NKC) load_chunk((kc + 2) % NSTAGE, kc + 2);

        const uint32_t sA = sb + (kc % NSTAGE) * STAGEB;
        const uint32_t sB = sA + TILEB;

        #pragma unroll
        for (int ks = 0; ks < 4; ks++) {
            const int kb = ks * 32 + lcol;
            uint32_t a[4][4], b[2][4];
            #pragma unroll
            for (int i = 0; i < 4; i++)
                ldsm4(a[i], sA + (uint32_t)((warp_m * 64 + i * 16 + lrow) * (TSTR * 2) + kb));
            #pragma unroll
            for (int jp = 0; jp < 2; jp++)
                ldsm4(b[jp], sB + (uint32_t)((warp_n * 32 + jp * 16 + lrow) * (TSTR * 2) + kb));
            #pragma unroll
            for (int i = 0; i < 4; i++) {
                mma16816(acc[i][0], a[i], b[0][0], b[0][2]);
                mma16816(acc[i][1], a[i], b[0][1], b[0][3]);
                mma16816(acc[i][2], a[i], b[1][0], b[1][2]);
                mma16816(acc[i][3], a[i], b[1][1], b[1][3]);
            }
        }
    }

    #pragma unroll
    for (int j = 0; j < 4; j++) {
        const int col = bn + warp_n * 32 + j * 8 + (lane & 3) * 2;
        const float b0 = bias[col], b1 = bias[col + 1];
        #pragma unroll
        for (int i = 0; i < 4; i++) {
            const int row = bm + warp_m * 64 + i * 16 + (lane >> 2);
            float2 o0, o1;
            o0.x = acc[i][j][0] + b0; o0.y = acc[i][j][1] + b1;
            o1.x = acc[i][j][2] + b0; o1.y = acc[i][j][3] + b1;
            *(float2*)(C + (size_t)row * VOCAB + col)       = o0;
            *(float2*)(C + (size_t)(row + 8) * VOCAB + col) = o1;
        }
    }
}

// ---------------- launch ----------------
extern "C" void kernel_launch(void* const* d_in, const int* in_sizes, int n_in,
                              void* d_out, int out_size) {
    const float* enc_out = (const float*)d_in[0];
    const int*   enc_mask= (const int*)  d_in[1];
    const int*   y_in    = (const int*)  d_in[2];
    const float* emb     = (const float*)d_in[3];
    const float* W_h     = (const float*)d_in[4];
    const float* W_s     = (const float*)d_in[5];
    const float* v       = (const float*)d_in[6];
    const float* Wih     = (const float*)d_in[7];
    const float* Whh     = (const float*)d_in[8];
    const float* bih     = (const float*)d_in[9];
    const float* bhh     = (const float*)d_in[10];
    const float* out_W   = (const float*)d_in[11];
    const float* out_b   = (const float*)d_in[12];

    float* out        = (float*)d_out;
    float* out_logits = out;
    float* out_alpha  = out + (size_t)Bsz * Ulen * VOCAB;

    cudaFuncSetAttribute(wh_kernel, cudaFuncAttributeMaxDynamicSharedMemorySize, WH_SMEM);
    cudaFuncSetAttribute(decoder_kernel, cudaFuncAttributeMaxDynamicSharedMemorySize, SMEM_DEC);
    cudaFuncSetAttribute(tc_gemm, cudaFuncAttributeMaxDynamicSharedMemorySize, GSMEM);

    wh_kernel<<<128, 512, WH_SMEM>>>(enc_out, W_h);
    convW_kernel<<<8192, 256>>>(out_W);
    transWs_kernel<<<DECD, ATTND>>>(W_s);
    decoder_kernel<<<NB, NTD, SMEM_DEC>>>(enc_out, enc_mask, y_in, emb, v,
                                          Wih, Whh, bih, bhh, out_alpha);
    dim3 gg((Bsz * Ulen) / BM, VOCAB / BN);
    tc_gemm<<<gg, 256, GSMEM>>>(out_b, out_logits);
}

// round 14
// speedup vs baseline: 1.5368x; 1.5368x over previous
#include <cuda_runtime.h>
#include <cuda_bf16.h>
#include <math.h>
#include <stdint.h>

#define Bsz   32
#define Tlen  128
#define Ulen  64
#define ENCD  512
#define DECD  512
#define ATTND 256
#define EMBD  256
#define VOCAB 32000
#define GIN   768     // EMB + ENC
#define G3    1536    // 3 * DEC
#define HCW   1024    // DEC + ENC

#define NB  132
#define NTD 512        // decoder threads per CTA (16 warps)

// ---------------- scratch (static device globals; no allocation) ----------------
__device__ float g_Wh[Bsz * Tlen * ATTND];          // 4 MB
__device__ float g_Ws[Bsz * ATTND];
__device__ float g_c[Bsz * ENCD];
__device__ float g_h[Bsz * DECD];
__device__ float g_gh[Bsz * G3];
__device__ unsigned g_barc;                          // zero-init
__device__ unsigned g_barg;                          // zero-init

// bf16 hi/lo split operands for the tensor-core logits GEMM
__device__ __nv_bfloat16 g_Whi[(size_t)VOCAB * HCW];   // 65.5 MB
__device__ __nv_bfloat16 g_Wlo[(size_t)VOCAB * HCW];   // 65.5 MB
__device__ __nv_bfloat16 g_Ahi[(size_t)Bsz * Ulen * HCW];  // 4 MB
__device__ __nv_bfloat16 g_Alo[(size_t)Bsz * Ulen * HCW];  // 4 MB

// ---------------- helpers ----------------
__device__ __forceinline__ float dot4(float4 a, float4 b) {
    return fmaf(a.x, b.x, fmaf(a.y, b.y, fmaf(a.z, b.z, a.w * b.w)));
}
__device__ __forceinline__ float wsum(float x) {
    x += __shfl_xor_sync(0xffffffffu, x, 16);
    x += __shfl_xor_sync(0xffffffffu, x, 8);
    x += __shfl_xor_sync(0xffffffffu, x, 4);
    x += __shfl_xor_sync(0xffffffffu, x, 2);
    x += __shfl_xor_sync(0xffffffffu, x, 1);
    return x;
}
__device__ __forceinline__ float wmax(float x) {
    x = fmaxf(x, __shfl_xor_sync(0xffffffffu, x, 16));
    x = fmaxf(x, __shfl_xor_sync(0xffffffffu, x, 8));
    x = fmaxf(x, __shfl_xor_sync(0xffffffffu, x, 4));
    x = fmaxf(x, __shfl_xor_sync(0xffffffffu, x, 2));
    x = fmaxf(x, __shfl_xor_sync(0xffffffffu, x, 1));
    return x;
}

__device__ __forceinline__ void grid_barrier() {
    __syncthreads();
    if (threadIdx.x == 0) {
        volatile unsigned* genp = &g_barg;
        unsigned gen = *genp;
        __threadfence();
        unsigned arrived = atomicAdd(&g_barc, 1u);
        if (arrived == NB - 1) {
            g_barc = 0;
            __threadfence();
            *genp = gen + 1;
        } else {
            while (*genp == gen) { }
            __threadfence();
        }
    }
    __syncthreads();
}

__device__ __forceinline__ void cpa16(uint32_t dst, const void* src) {
    asm volatile("cp.async.cg.shared.global [%0], [%1], 16;" :: "r"(dst), "l"(src));
}
__device__ __forceinline__ uint32_t smem_u32(const void* p) {
    uint32_t a;
    asm("{ .reg .u64 t; cvta.to.shared.u64 t, %1; cvt.u32.u64 %0, t; }" : "=r"(a) : "l"(p));
    return a;
}
__device__ __forceinline__ void ldsm4(uint32_t* r, uint32_t addr) {
    asm volatile("ldmatrix.sync.aligned.m8n8.x4.shared.b16 {%0,%1,%2,%3}, [%4];"
                 : "=r"(r[0]), "=r"(r[1]), "=r"(r[2]), "=r"(r[3]) : "r"(addr));
}

// ---------------- kernel 1: Wh = enc_out @ W_h  (tiled, W_h staged in smem) ----------------
#define WH_SMEM ((32 * 64 + 64 * ATTND) * 4)   // sE 8KB + sW 64KB = 72KB
__global__ __launch_bounds__(512) void wh_kernel(const float* __restrict__ enc_out,
                                                 const float* __restrict__ W_h) {
    extern __shared__ float ws[];
    float* sE = ws;            // [32][64]
    float* sW = ws + 32 * 64;  // [64][256]
    const int tid  = threadIdx.x;
    const int col  = tid & 255;
    const int half = tid >> 8;           // 0..1
    const int r0   = half * 16;
    const int bt0  = blockIdx.x * 32;

    float acc[16];
    #pragma unroll
    for (int r = 0; r < 16; r++) acc[r] = 0.f;

    for (int kc = 0; kc < 8; kc++) {
        {
            const int row = tid >> 4, kq = tid & 15;
            *(float4*)&sE[row * 64 + kq * 4] =
                *(const float4*)&enc_out[(size_t)(bt0 + row) * ENCD + kc * 64 + kq * 4];
        }
        #pragma unroll
        for (int it = 0; it < 8; it++) {
            const int idx = tid + it * 512;
            const int kk = idx >> 6, cq = idx & 63;
            *(float4*)&sW[kk * 256 + cq * 4] =
                *(const float4*)&W_h[(size_t)(kc * 64 + kk) * ATTND + cq * 4];
        }
        __syncthreads();
        #pragma unroll 4
        for (int kk = 0; kk < 64; kk++) {
            const float w = sW[kk * 256 + col];
            #pragma unroll
            for (int r = 0; r < 16; r++)
                acc[r] = fmaf(sE[(r0 + r) * 64 + kk], w, acc[r]);
        }
        __syncthreads();
    }
    #pragma unroll
    for (int r = 0; r < 16; r++)
        g_Wh[(size_t)(bt0 + r0 + r) * ATTND + col] = acc[r];
}

// ---------------- conversion kernel: W fp32 -> bf16 hi/lo split ----------------
__global__ __launch_bounds__(256) void convW_kernel(const float* __restrict__ W) {
    const size_t n4 = (size_t)VOCAB * HCW / 4;
    const size_t stride = (size_t)gridDim.x * blockDim.x;
    for (size_t i = (size_t)blockIdx.x * blockDim.x + threadIdx.x; i < n4; i += stride) {
        float4 v = ((const float4*)W)[i];
        __nv_bfloat16 h0 = __float2bfloat16(v.x);
        __nv_bfloat16 h1 = __float2bfloat16(v.y);
        __nv_bfloat16 h2 = __float2bfloat16(v.z);
        __nv_bfloat16 h3 = __float2bfloat16(v.w);
        __nv_bfloat162 H01, H23, L01, L23;
        H01.x = h0; H01.y = h1; H23.x = h2; H23.y = h3;
        L01.x = __float2bfloat16(v.x - __bfloat162float(h0));
        L01.y = __float2bfloat16(v.y - __bfloat162float(h1));
        L23.x = __float2bfloat16(v.z - __bfloat162float(h2));
        L23.y = __float2bfloat16(v.w - __bfloat162float(h3));
        ((__nv_bfloat162*)g_Whi)[2 * i]     = H01;
        ((__nv_bfloat162*)g_Whi)[2 * i + 1] = H23;
        ((__nv_bfloat162*)g_Wlo)[2 * i]     = L01;
        ((__nv_bfloat162*)g_Wlo)[2 * i + 1] = L23;
    }
}

// ---------------- kernel 2: persistent decoder (R10-proven version) ----------------
// smem float layout:
//   [0,1024)        sws   : W_s slice, 2 cols x 512   (CTA ci<128, cols 2ci..2ci+1)
//   [1024,9216)     swhh  : Whh slice, 16 rows x 512  (CTA 32<=ci<128)
//   [9216,18432)    swih  : Wih slice, 12 rows x 768  (CTA ci<128, d0=4ci)
//   [18432,34816)   sh    : full h, 32 x 512
//   [34816,34944)   se
//   [34944,35072)   salpha
//   [35072,35328)   swsb
//   [35328,35584)   sv
//   [35584,35648)   sred
#define SMEM_DEC (35648 * 4)

__global__ __launch_bounds__(NTD) void decoder_kernel(
    const float* __restrict__ enc_out, const int* __restrict__ enc_mask,
    const int* __restrict__ y_in, const float* __restrict__ emb,
    const float* __restrict__ W_s, const float* __restrict__ v,
    const float* __restrict__ Wih, const float* __restrict__ Whh,
    const float* __restrict__ bih, const float* __restrict__ bhh,
    float* __restrict__ out_alpha)
{
    extern __shared__ float sm[];
    float* sws    = sm;
    float* swhh   = sm + 1024;
    float* swih   = sm + 9216;
    float* sh     = sm + 18432;
    float* se     = sm + 34816;
    float* salpha = sm + 34944;
    float* swsb   = sm + 35072;
    float* sv     = sm + 35328;
    float* sred   = sm + 35584;

    const int ci   = blockIdx.x;
    const int tid  = threadIdx.x;
    const int lane = tid & 31;
    const int wid  = tid >> 5;

    // ---- one-time: load weight slices into smem ----
    if (ci < 128) {
        const int c0 = ci * 2;
        for (int i = tid; i < 1024; i += NTD)
            sws[i] = W_s[(size_t)(i & 511) * ATTND + c0 + (i >> 9)];
        const int d0 = ci * 4;
        for (int i = tid; i < 9216; i += NTD) {
            const int r = i / GIN, k = i - r * GIN;
            const int g = r >> 2, dL = r & 3;
            swih[i] = Wih[(size_t)(g * DECD + d0 + dL) * GIN + k];
        }
    }
    if (ci >= 32 && ci < 128) {
        const int r0 = (ci - 32) * 16;
        for (int i = tid; i < 8192; i += NTD)
            swhh[i] = Whh[(size_t)(r0 + (i >> 9)) * DECD + (i & 511)];
    }
    if (ci < 32) {
        for (int i = tid; i < ATTND; i += NTD) sv[i] = v[i];
    }
    for (int i = ci * NTD + tid; i < Bsz * DECD; i += NB * NTD) g_h[i] = 0.f;
    grid_barrier();

    for (int u = 0; u < Ulen; u++) {
        // ================= Phase A: cache h, compute Ws columns =================
        if (ci < 128) {
            float4* sh4 = (float4*)sh;
            const float4* gh4 = (const float4*)g_h;
            for (int i = tid; i < (Bsz * DECD) / 4; i += NTD) sh4[i] = gh4[i];
            __syncthreads();
            #pragma unroll
            for (int j = 0; j < 4; j++) {
                const int k = wid * 4 + j;            // 0..63
                const int colL = k >> 5, b = k & 31;
                const float4* hb = (const float4*)(sh + b * DECD);
                const float4* wc = (const float4*)(sws + colL * DECD);
                float acc = 0.f;
                #pragma unroll
                for (int q = 0; q < 4; q++) {
                    const int i4 = q * 32 + lane;
                    acc += dot4(hb[i4], wc[i4]);
                }
                acc = wsum(acc);
                if (lane == 0) g_Ws[b * ATTND + ci * 2 + colL] = acc;
            }
        }
        grid_barrier();

        // ================= Phase BC: attention (CTAs 0..31) || gh (CTAs 32..127) ====
        if (ci < 32) {
            const int b = ci;
            for (int i = tid; i < ATTND; i += NTD) swsb[i] = g_Ws[b * ATTND + i];
            __syncthreads();
            #pragma unroll
            for (int j = 0; j < 8; j++) {
                const int t = wid * 8 + j;
                const float4* whp = (const float4*)(g_Wh + ((size_t)b * Tlen + t) * ATTND);
                const float4* wsp = (const float4*)swsb;
                const float4* vp  = (const float4*)sv;
                float acc = 0.f;
                #pragma unroll
                for (int q = 0; q < 2; q++) {
                    const int i4 = q * 32 + lane;
                    float4 w4 = whp[i4], s4 = wsp[i4], v4 = vp[i4];
                    acc += v4.x * tanhf(w4.x + s4.x);
                    acc += v4.y * tanhf(w4.y + s4.y);
                    acc += v4.z * tanhf(w4.z + s4.z);
                    acc += v4.w * tanhf(w4.w + s4.w);
                }
                acc = wsum(acc);
                if (lane == 0) se[t] = enc_mask[b * Tlen + t] ? acc : -INFINITY;
            }
            __syncthreads();
            if (tid < 128) {
                float m = wmax(se[tid]);
                if (lane == 0) sred[wid] = m;
            }
            __syncthreads();
            if (tid == 0)
                sred[8] = fmaxf(fmaxf(sred[0], sred[1]), fmaxf(sred[2], sred[3]));
            __syncthreads();
            if (tid < 128) {
                const float p = expf(se[tid] - sred[8]);
                salpha[tid] = p;
                const float s = wsum(p);
                if (lane == 0) sred[16 + wid] = s;
            }
            __syncthreads();
            if (tid == 0)
                sred[9] = sred[16] + sred[17] + sred[18] + sred[19];
            __syncthreads();
            if (tid < 128) {
                const float al = salpha[tid] / sred[9];
                salpha[tid] = al;
                out_alpha[((size_t)b * Ulen + u) * Tlen + tid] = al;
            }
            __syncthreads();
            {
                const float* ep = enc_out + (size_t)b * Tlen * ENCD + tid;
                float a0 = 0.f, a1 = 0.f, a2 = 0.f, a3 = 0.f;
                #pragma unroll 4
                for (int t = 0; t < Tlen; t += 4) {
                    a0 = fmaf(salpha[t + 0], ep[(t + 0) * ENCD], a0);
                    a1 = fmaf(salpha[t + 1], ep[(t + 1) * ENCD], a1);
                    a2 = fmaf(salpha[t + 2], ep[(t + 2) * ENCD], a2);
                    a3 = fmaf(salpha[t + 3], ep[(t + 3) * ENCD], a3);
                }
                const float cc = (a0 + a1) + (a2 + a3);
                g_c[b * ENCD + tid] = cc;
                const size_t hx = ((size_t)b * Ulen + u) * HCW + DECD + tid;
                const __nv_bfloat16 hi = __float2bfloat16(cc);
                g_Ahi[hx] = hi;
                g_Alo[hx] = __float2bfloat16(cc - __bfloat162float(hi));
            }
        } else if (ci < 128) {
            const int r0 = (ci - 32) * 16;
            const int b0 = wid * 2, b1 = b0 + 1;
            float4 h0r[4], h1r[4];
            const float4* h0p = (const float4*)(sh + b0 * DECD);
            const float4* h1p = (const float4*)(sh + b1 * DECD);
            #pragma unroll
            for (int q = 0; q < 4; q++) {
                h0r[q] = h0p[q * 32 + lane];
                h1r[q] = h1p[q * 32 + lane];
            }
            #pragma unroll 2
            for (int rL = 0; rL < 16; rL++) {
                const float4* wr = (const float4*)(swhh + rL * DECD);
                float a0 = 0.f, a1 = 0.f;
                #pragma unroll
                for (int q = 0; q < 4; q++) {
                    const float4 w4 = wr[q * 32 + lane];
                    a0 += dot4(h0r[q], w4);
                    a1 += dot4(h1r[q], w4);
                }
                a0 = wsum(a0); a1 = wsum(a1);
                if (lane == 0) {
                    const float bb = bhh[r0 + rL];
                    g_gh[b0 * G3 + r0 + rL] = a0 + bb;
                    g_gh[b1 * G3 + r0 + rL] = a1 + bb;
                }
            }
        }
        grid_barrier();

        // ================= Phase D: GRU gates, h_new (CTAs 0..127) =================
        if (ci < 128) {
            const int d0 = ci * 4;
            const int b0 = wid * 2, b1 = b0 + 1;
            float4 x0[6], x1[6];
            {
                const int y0 = y_in[b0 * Ulen + u];
                const int y1 = y_in[b1 * Ulen + u];
                const float4* e0 = (const float4*)(emb + (size_t)y0 * EMBD);
                const float4* e1 = (const float4*)(emb + (size_t)y1 * EMBD);
                const float4* c0p = (const float4*)(g_c + b0 * ENCD);
                const float4* c1p = (const float4*)(g_c + b1 * ENCD);
                #pragma unroll
                for (int q = 0; q < 6; q++) {
                    const int i4 = q * 32 + lane;
                    x0[q] = (i4 < 64) ? e0[i4] : c0p[i4 - 64];
                    x1[q] = (i4 < 64) ? e1[i4] : c1p[i4 - 64];
                }
            }
            #pragma unroll
            for (int dL = 0; dL < 4; dL++) {
                const int d = d0 + dL;
                float ir0 = 0.f, iz0 = 0.f, in0 = 0.f;
                float ir1 = 0.f, iz1 = 0.f, in1 = 0.f;
                const float4* wr = (const float4*)(swih + (0 * 4 + dL) * GIN);
                const float4* wz = (const float4*)(swih + (1 * 4 + dL) * GIN);
                const float4* wn = (const float4*)(swih + (2 * 4 + dL) * GIN);
                #pragma unroll
                for (int q = 0; q < 6; q++) {
                    const int i4 = q * 32 + lane;
                    const float4 a = wr[i4], z = wz[i4], n = wn[i4];
                    ir0 += dot4(x0[q], a); ir1 += dot4(x1[q], a);
                    iz0 += dot4(x0[q], z); iz1 += dot4(x1[q], z);
                    in0 += dot4(x0[q], n); in1 += dot4(x1[q], n);
                }
                ir0 = wsum(ir0); iz0 = wsum(iz0); in0 = wsum(in0);
                ir1 = wsum(ir1); iz1 = wsum(iz1); in1 = wsum(in1);
                if (lane == 0) {
                    const float br = bih[d], bz = bih[DECD + d], bn2 = bih[2 * DECD + d];
                    {
                        const float hr = g_gh[b0 * G3 + d];
                        const float hz = g_gh[b0 * G3 + DECD + d];
                        const float hn = g_gh[b0 * G3 + 2 * DECD + d];
                        const float r = 1.f / (1.f + expf(-(ir0 + br + hr)));
                        const float z = 1.f / (1.f + expf(-(iz0 + bz + hz)));
                        const float n = tanhf(in0 + bn2 + r * hn);
                        const float hp = g_h[b0 * DECD + d];
                        const float hnew = (1.f - z) * n + z * hp;
                        g_h[b0 * DECD + d] = hnew;
                        const size_t hx = ((size_t)b0 * Ulen + u) * HCW + d;
                        const __nv_bfloat16 hi = __float2bfloat16(hnew);
                        g_Ahi[hx] = hi;
                        g_Alo[hx] = __float2bfloat16(hnew - __bfloat162float(hi));
                    }
                    {
                        const float hr = g_gh[b1 * G3 + d];
                        const float hz = g_gh[b1 * G3 + DECD + d];
                        const float hn = g_gh[b1 * G3 + 2 * DECD + d];
                        const float r = 1.f / (1.f + expf(-(ir1 + br + hr)));
                        const float z = 1.f / (1.f + expf(-(iz1 + bz + hz)));
                        const float n = tanhf(in1 + bn2 + r * hn);
                        const float hp = g_h[b1 * DECD + d];
                        const float hnew = (1.f - z) * n + z * hp;
                        g_h[b1 * DECD + d] = hnew;
                        const size_t hx = ((size_t)b1 * Ulen + u) * HCW + d;
                        const __nv_bfloat16 hi = __float2bfloat16(hnew);
                        g_Ahi[hx] = hi;
                        g_Alo[hx] = __float2bfloat16(hnew - __bfloat162float(hi));
                    }
                }
            }
        }
        grid_barrier();
    }
}

// ---------------- kernel 3: bf16-split logits GEMM, 3-stage cp.async pipeline ----------------
#define BM 128
#define BN 128
#define BKE 64
#define NKC 48
#define TPAD 8
#define TSTR (BKE + TPAD)
#define TILEB (128 * TSTR * 2)
#define STAGEB (2 * TILEB)          // 36864
#define NSTAGE 3
#define GSMEM (NSTAGE * STAGEB)     // 110592

__device__ __forceinline__ void mma16816(float* c, const uint32_t* a, uint32_t b0, uint32_t b1) {
    asm volatile(
        "mma.sync.aligned.m16n8k16.row.col.f32.bf16.bf16.f32 "
        "{%0,%1,%2,%3}, {%4,%5,%6,%7}, {%8,%9}, {%0,%1,%2,%3};"
        : "+f"(c[0]), "+f"(c[1]), "+f"(c[2]), "+f"(c[3])
        : "r"(a[0]), "r"(a[1]), "r"(a[2]), "r"(a[3]), "r"(b0), "r"(b1));
}

__global__ __launch_bounds__(256, 2) void tc_gemm(const float* __restrict__ bias,
                                                  float* __restrict__ C)
{
    extern __shared__ char smemc[];
    const uint32_t sb = smem_u32(smemc);
    const int tid  = threadIdx.x;
    const int wid  = tid >> 5;
    const int lane = tid & 31;
    const int warp_m = wid >> 2;
    const int warp_n = wid & 3;
    const int bm = blockIdx.x * BM;
    const int bn = blockIdx.y * BN;

    const int lrow = lane & 15;
    const int lcol = (lane >> 4) * 16;

    float acc[4][4][4];
    #pragma unroll
    for (int i = 0; i < 4; i++)
        #pragma unroll
        for (int j = 0; j < 4; j++)
            #pragma unroll
            for (int r = 0; r < 4; r++) acc[i][j][r] = 0.f;

    auto load_chunk = [&](int stage, int kc) {
        const int p  = kc >> 4;
        const int ko = (kc & 15) * BKE;
        const __nv_bfloat16* Asrc = (p < 2) ? g_Ahi : g_Alo;
        const __nv_bfloat16* Bsrc = (p == 1) ? g_Wlo : g_Whi;
        const uint32_t sA = sb + stage * STAGEB;
        const uint32_t sB = sA + TILEB;
        #pragma unroll
        for (int it = 0; it < 8; it++) {
            const int i = tid + it * 256;
            const int row  = (i >> 3) & 127;
            const int unit = i & 7;
            const uint32_t doff = (uint32_t)(row * (TSTR * 2) + unit * 16);
            if (i < 1024) {
                cpa16(sA + doff, Asrc + (size_t)(bm + row) * HCW + ko + unit * 8);
            } else {
                cpa16(sB + doff, Bsrc + (size_t)(bn + row) * HCW + ko + unit * 8);
            }
        }
        asm volatile("cp.async.commit_group;");
    };

    load_chunk(0, 0);
    load_chunk(1, 1);

    #pragma unroll 1
    for (int kc = 0; kc < NKC; kc++) {
        if (kc == NKC - 1) {
            asm volatile("cp.async.wait_group 0;" ::: "memory");
        } else {
            asm volatile("cp.async.wait_group 1;" ::: "memory");
        }
        __syncthreads();   // chunk kc visible; stage (kc+2)%3 free (computed at kc-1)

        if (kc + 2 < NKC) load_chunk((kc + 2) % NSTAGE, kc + 2);

        const uint32_t sA = sb + (kc % NSTAGE) * STAGEB;
        const uint32_t sB = sA + TILEB;

        #pragma unroll
        for (int ks = 0; ks < 4; ks++) {
            const int kb = ks * 32 + lcol;
            uint32_t a[4][4], b[2][4];
            #pragma unroll
            for (int i = 0; i < 4; i++)
                ldsm4(a[i], sA + (uint32_t)((warp_m * 64 + i * 16 + lrow) * (TSTR * 2) + kb));
            #pragma unroll
            for (int jp = 0; jp < 2; jp++)
                ldsm4(b[jp], sB + (uint32_t)((warp_n * 32 + jp * 16 + lrow) * (TSTR * 2) + kb));
            #pragma unroll
            for (int i = 0; i < 4; i++) {
                mma16816(acc[i][0], a[i], b[0][0], b[0][2]);
                mma16816(acc[i][1], a[i], b[0][1], b[0][3]);
                mma16816(acc[i][2], a[i], b[1][0], b[1][2]);
                mma16816(acc[i][3], a[i], b[1][1], b[1][3]);
            }
        }
    }

    #pragma unroll
    for (int j = 0; j < 4; j++) {
        const int col = bn + warp_n * 32 + j * 8 + (lane & 3) * 2;
        const float b0 = bias[col], b1 = bias[col + 1];
        #pragma unroll
        for (int i = 0; i < 4; i++) {
            const int row = bm + warp_m * 64 + i * 16 + (lane >> 2);
            float2 o0, o1;
            o0.x = acc[i][j][0] + b0; o0.y = acc[i][j][1] + b1;
            o1.x = acc[i][j][2] + b0; o1.y = acc[i][j][3] + b1;
            *(float2*)(C + (size_t)row * VOCAB + col)       = o0;
            *(float2*)(C + (size_t)(row + 8) * VOCAB + col) = o1;
        }
    }
}

// ---------------- launch ----------------
extern "C" void kernel_launch(void* const* d_in, const int* in_sizes, int n_in,
                              void* d_out, int out_size) {
    const float* enc_out = (const float*)d_in[0];
    const int*   enc_mask= (const int*)  d_in[1];
    const int*   y_in    = (const int*)  d_in[2];
    const float* emb     = (const float*)d_in[3];
    const float* W_h     = (const float*)d_in[4];
    const float* W_s     = (const float*)d_in[5];
    const float* v       = (const float*)d_in[6];
    const float* Wih     = (const float*)d_in[7];
    const float* Whh     = (const float*)d_in[8];
    const float* bih     = (const float*)d_in[9];
    const float* bhh     = (const float*)d_in[10];
    const float* out_W   = (const float*)d_in[11];
    const float* out_b   = (const float*)d_in[12];

    float* out        = (float*)d_out;
    float* out_logits = out;
    float* out_alpha  = out + (size_t)Bsz * Ulen * VOCAB;

    cudaFuncSetAttribute(wh_kernel, cudaFuncAttributeMaxDynamicSharedMemorySize, WH_SMEM);
    cudaFuncSetAttribute(decoder_kernel, cudaFuncAttributeMaxDynamicSharedMemorySize, SMEM_DEC);
    cudaFuncSetAttribute(tc_gemm, cudaFuncAttributeMaxDynamicSharedMemorySize, GSMEM);

    wh_kernel<<<128, 512, WH_SMEM>>>(enc_out, W_h);
    convW_kernel<<<8192, 256>>>(out_W);
    decoder_kernel<<<NB, NTD, SMEM_DEC>>>(enc_out, enc_mask, y_in, emb, W_s, v,
                                          Wih, Whh, bih, bhh, out_alpha);
    dim3 gg((Bsz * Ulen) / BM, VOCAB / BN);
    tc_gemm<<<gg, 256, GSMEM>>>(out_b, out_logits);
}